// round 8
// baseline (speedup 1.0000x reference)
#include <cuda_runtime.h>
#include <cstdint>

// ---------------- problem constants ----------------
#define BN   32
#define TN   4096
#define CINN 165
#define EDIM 64
#define NEMB 512
#define NTOK (BN*TN)          // 131072
#define TILE 32               // tokens per CTA (16 interleaved pairs)
#define NBLK (NTOK/TILE)      // 4096
#define S2   18               // token-pair row stride (ULLs) -> 36 floats
#define SF   36               // row stride in floats
#define DEC_ELEMS (NTOK*CINN) // 21626880
#define THREADS 128

// shared layout (floats)
#define SM_A   0
#define SM_B   (256*SF)             // 9216
#define SM_W   (2*256*SF)           // 18432
#define WBUFF  4096                 // floats per weight buffer (KBT*CW*2 == 4096)
#define SM_AUX (SM_W + 2*WBUFF)     // 26624
#define SM_FLOATS (SM_AUX + 128 + 64 + 8)
#define SMEM_BYTES (SM_FLOATS*4)    // ~105 KB -> 2 CTAs/SM

typedef unsigned long long ULL;

// transposed+padded+duplicated weights and bias, built by prep_kernel
__device__ float g_Wd[569344];
__device__ float g_bias[2496];
__device__ float g_part[NBLK];
__device__ unsigned int g_count;

// layer metadata: {w_in_idx, b_in_idx, CIN, COUT, KPAD, CW, woff(non-dup), boff}
__constant__ int c_layers[15][8] = {
    { 1,  2, 165, 128, 176, 128,      0,    0},
    { 3,  4, 128, 256, 128, 256,  22528,  128},
    { 5,  6, 256, 256, 256, 256,  55296,  384},
    { 7,  8, 256,  32, 256,  32, 120832,  640},
    { 9, 10,  32, 256,  32, 256, 129024,  672},
    {11, 12, 256,  32, 256,  32, 137216,  928},
    {13, 14,  32, 256,  32, 256, 145408,  960},
    {15, 16, 256,  64, 256,  64, 153600, 1216},
    {18, 19,  64, 256,  64, 256, 169984, 1280},
    {20, 21, 256,  32, 256,  32, 186368, 1536},
    {22, 23,  32, 256,  32, 256, 194560, 1568},
    {24, 25, 256,  32, 256,  32, 202752, 1824},
    {26, 27,  32, 256,  32, 256, 210944, 1856},
    {28, 29, 256, 128, 256, 128, 219136, 2112},
    {30, 31, 128, 165, 128, 256, 251904, 2240},   // L14 padded 192->256
};

// ---------------- f32x2 helpers ----------------
__device__ __forceinline__ ULL pack2(float x, float y) {
    ULL r; asm("mov.b64 %0, {%1, %2};" : "=l"(r) : "f"(x), "f"(y)); return r;
}
__device__ __forceinline__ void unpack2(ULL v, float& x, float& y) {
    asm("mov.b64 {%0, %1}, %2;" : "=f"(x), "=f"(y) : "l"(v));
}
__device__ __forceinline__ void fma2(ULL& d, ULL a, ULL b) {
    asm("fma.rn.f32x2 %0, %1, %2, %0;" : "+l"(d) : "l"(a), "l"(b));
}
__device__ __forceinline__ ULL relu2(ULL v) {
    float x, y; unpack2(v, x, y);
    return pack2(fmaxf(x, 0.f), fmaxf(y, 0.f));
}
__device__ __forceinline__ uint32_t smem_u32(const void* p) {
    uint32_t a;
    asm("{ .reg .u64 t; cvta.to.shared.u64 t, %1; cvt.u32.u64 %0, t; }" : "=r"(a) : "l"(p));
    return a;
}
__device__ __forceinline__ void cp_async16(uint32_t dst, const void* src) {
    asm volatile("cp.async.cg.shared.global [%0], [%1], 16;\n" :: "r"(dst), "l"(src));
}
// token j (0..31) -> float column in interleaved pair layout
__device__ __forceinline__ int jcol(int j) { return ((j & 15) << 1) | (j >> 4); }

// ---------------- prep: transpose + pad + duplicate weights ----------------
struct Params { const float* in[32]; float* out; int out_size; };

__global__ void prep_kernel(Params P) {
    const int L = blockIdx.x;
    const int CIN  = c_layers[L][2], COUT = c_layers[L][3];
    const int KPAD = c_layers[L][4], CW   = c_layers[L][5];
    const int woff = c_layers[L][6] * 2, boff = c_layers[L][7];
    const float* W = P.in[c_layers[L][0]];
    const float* b = P.in[c_layers[L][1]];
    for (int e = threadIdx.x; e < KPAD * CW; e += blockDim.x) {
        int k = e / CW, c = e - (e / CW) * CW;
        float v = (k < CIN && c < COUT) ? W[c * CIN + k] : 0.f;
        g_Wd[woff + 2 * e]     = v;
        g_Wd[woff + 2 * e + 1] = v;
    }
    for (int c = threadIdx.x; c < CW; c += blockDim.x)
        g_bias[boff + c] = (c < COUT) ? b[c] : 0.f;
}

// ---------------- fused 1x1-conv layer (broadcast-act layout) ----------------
// Activations: ULL rows A2[k][p] = (tok p, tok p+16), p = 0..15, row stride S2.
// 128 threads = 4 warps. Warp lane-dim spans channels -> act reads broadcast.
//   CW=256: lane l -> ch {64w+2l, +1}, pairs 0..15   (acc 2x16)
//   CW=128: lane l -> ch 32w+l,        pairs 0..15   (acc 1x16)
//   CW= 64: lane l -> ch 16w+(l&15),   pairs (l>>4)*8..+7  (acc 1x8)
//   CW= 32: lane l -> ch 8w+(l&7),     pairs (l>>3)*4..+3  (acc 1x4)
template<int CW, int KPAD, int KBT, bool PRE, bool POST, bool RES>
__device__ __noinline__ void conv_layer(const float* __restrict__ Wd,
                                        const float* __restrict__ bias,
                                        const ULL* __restrict__ IN2,
                                        ULL* __restrict__ OUT2,
                                        float* __restrict__ Ws, int tid)
{
    constexpr int NCH = (CW == 256) ? 2 : 1;
    constexpr int NP  = (CW >= 128) ? 16 : (CW == 64 ? 8 : 4);
    constexpr int NK  = KPAD / KBT;
    constexpr int CHUNKF = KBT * CW * 2;
    static_assert(CHUNKF <= WBUFF, "chunk too big");

    const int l = tid & 31;
    const int w = tid >> 5;
    int ch0, pbase;
    if constexpr (CW == 256)      { ch0 = 64 * w + 2 * l;     pbase = 0; }
    else if constexpr (CW == 128) { ch0 = 32 * w + l;         pbase = 0; }
    else if constexpr (CW == 64)  { ch0 = 16 * w + (l & 15);  pbase = (l >> 4) * 8; }
    else                          { ch0 = 8 * w + (l & 7);    pbase = (l >> 3) * 4; }

    float bv[NCH];
#pragma unroll
    for (int m = 0; m < NCH; m++) bv[m] = __ldg(bias + ch0 + m);

    ULL acc[NCH][NP];
#pragma unroll
    for (int m = 0; m < NCH; m++)
#pragma unroll
        for (int i = 0; i < NP; i++) acc[m][i] = 0ull;

    __syncthreads();   // prev-layer activations visible; Ws free

    // stage chunk 0 (linear memcpy of dup'd weights)
    {
        const float4* src = reinterpret_cast<const float4*>(Wd);
        float4* dst = reinterpret_cast<float4*>(Ws);
#pragma unroll
        for (int i = tid; i < CHUNKF / 4; i += THREADS)
            cp_async16(smem_u32(dst + i), src + i);
        asm volatile("cp.async.commit_group;\n" ::: "memory");
    }

    for (int kb = 0; kb < NK; kb++) {
        asm volatile("cp.async.wait_group 0;\n" ::: "memory");
        __syncthreads();
        if (kb + 1 < NK) {
            const float4* src = reinterpret_cast<const float4*>(Wd + (kb + 1) * CHUNKF);
            float4* dst = reinterpret_cast<float4*>(Ws + ((kb + 1) & 1) * WBUFF);
#pragma unroll
            for (int i = tid; i < CHUNKF / 4; i += THREADS)
                cp_async16(smem_u32(dst + i), src + i);
            asm volatile("cp.async.commit_group;\n" ::: "memory");
        }

        const ULL* Wk = reinterpret_cast<const ULL*>(Ws + (kb & 1) * WBUFF);
        const ULL* inb = IN2 + (kb * KBT) * S2 + pbase;

#pragma unroll 8
        for (int kk = 0; kk < KBT; kk++) {
            // acts: NP pairs, warp-broadcast LDS.128
            ULL t[NP];
            const ulonglong2* ar = reinterpret_cast<const ulonglong2*>(inb + kk * S2);
#pragma unroll
            for (int i = 0; i < NP / 2; i++) {
                ulonglong2 p = ar[i];
                t[2 * i] = p.x; t[2 * i + 1] = p.y;
            }
            if (PRE) {
#pragma unroll
                for (int i = 0; i < NP; i++) t[i] = relu2(t[i]);
            }
            // weights: dup'd pairs, conflict-free
            const ULL* wrow = Wk + kk * CW;   // CW ULLs per k-row
            ULL wd[NCH];
            if constexpr (NCH == 2) {
                ulonglong2 q = *reinterpret_cast<const ulonglong2*>(wrow + ch0);
                wd[0] = q.x; wd[1] = q.y;
            } else {
                wd[0] = wrow[ch0];
            }
#pragma unroll
            for (int m = 0; m < NCH; m++)
#pragma unroll
                for (int i = 0; i < NP; i++)
                    fma2(acc[m][i], wd[m], t[i]);
        }
    }

    // epilogue: thread exclusively owns (ch, pair-range) slots of OUT2
#pragma unroll
    for (int m = 0; m < NCH; m++) {
        ULL* orow = OUT2 + (ch0 + m) * S2 + pbase;
#pragma unroll
        for (int i = 0; i < NP / 2; i++) {
            float x0, y0, x1, y1;
            unpack2(acc[m][2 * i],     x0, y0);
            unpack2(acc[m][2 * i + 1], x1, y1);
            x0 += bv[m]; y0 += bv[m]; x1 += bv[m]; y1 += bv[m];
            if (RES) {
                ulonglong2 e = *reinterpret_cast<const ulonglong2*>(orow + 2 * i);
                float ex0, ey0, ex1, ey1;
                unpack2(e.x, ex0, ey0); unpack2(e.y, ex1, ey1);
                x0 += ex0; y0 += ey0; x1 += ex1; y1 += ey1;
            }
            if (POST) {
                x0 = fmaxf(x0, 0.f); y0 = fmaxf(y0, 0.f);
                x1 = fmaxf(x1, 0.f); y1 = fmaxf(y1, 0.f);
            }
            ulonglong2 o;
            o.x = pack2(x0, y0); o.y = pack2(x1, y1);
            *reinterpret_cast<ulonglong2*>(orow + 2 * i) = o;
        }
    }
}

#define LCONV(L, CW, KPAD, KBT, PRE, POST, RES, INB, OUTB) \
    conv_layer<CW, KPAD, KBT, PRE, POST, RES>(g_Wd + 2*c_layers[L][6], g_bias + c_layers[L][7], INB, OUTB, Ws, tid)

// ---------------- main fused kernel ----------------
__global__ void __launch_bounds__(THREADS, 2) vqvae_kernel(Params P)
{
    extern __shared__ float sm[];
    float* Af   = sm + SM_A;
    float* Bf   = sm + SM_B;
    float* Ws   = sm + SM_W;
    float* enp  = sm + SM_AUX;       // [128]
    float* en   = enp + 128;         // [64]
    float* wsum = en + 64;           // [8]
    ULL* A2 = reinterpret_cast<ULL*>(Af);
    ULL* B2 = reinterpret_cast<ULL*>(Bf);

    const int tid = threadIdx.x;
    const int n0  = blockIdx.x * TILE;

    // ---- load x tile into interleaved-pair layout; zero-pad rows 165..175 ----
    const float* x = P.in[0];
    for (int idx = tid; idx < 176 * TILE; idx += THREADS) {
        int c = idx % 176;
        int j = idx / 176;
        Af[c * SF + jcol(j)] = (c < CINN) ? x[(n0 + j) * CINN + c] : 0.f;
    }

    // ---- encoder ----
    LCONV(0, 128, 176, 16, false, true,  false, A2, B2);
    LCONV(1, 256, 128,  8, false, true,  false, B2, A2);
    LCONV(2, 256, 256,  8, false, false, false, A2, B2);
    LCONV(3,  32, 256, 64, true,  true,  false, B2, A2);
    LCONV(4, 256,  32,  8, false, false, true,  A2, B2);
    LCONV(5,  32, 256, 64, true,  true,  false, B2, A2);
    LCONV(6, 256,  32,  8, false, false, true,  A2, B2);
    LCONV(7,  64, 256, 32, true,  false, false, B2, A2);   // z -> A rows 0..63

    // ---- vector quantize (z in A rows 0..63, pair layout) ----
    {
        const float* embed = P.in[17];
        float* Es = Ws;                 // [64 d][64 codes] = 16KB
        const int j = tid >> 2;         // token 0..31
        const int jc = jcol(j);
        const int q = tid & 3;          // code 16-chunk within 64-code block
        float best = 3.4e38f; int bidx = 0;

        for (int cb = 0; cb < 8; cb++) {
            __syncthreads();
            float sq = 0.f;
#pragma unroll
            for (int i = 0; i < 32; i++) {
                int idx = i * THREADS + tid;
                int kk = idx & 63, d = idx >> 6;
                float v = __ldg(embed + d * NEMB + cb * 64 + kk);
                Es[d * 64 + kk] = v;
                sq += v * v;            // all iterations share kk = tid&63
            }
            enp[tid] = sq;
            __syncthreads();
            if (tid < 64) en[tid] = enp[tid] + enp[tid + 64];
            __syncthreads();

            ULL dot[8];
#pragma unroll
            for (int g = 0; g < 8; g++) dot[g] = 0ull;
#pragma unroll 8
            for (int d = 0; d < EDIM; d++) {
                float z = Af[d * SF + jc];
                ULL z2 = pack2(z, z);
                const ulonglong2* er = reinterpret_cast<const ulonglong2*>(Es + d * 64 + q * 16);
                ulonglong2 e0 = er[0], e1 = er[1], e2 = er[2], e3 = er[3];
                fma2(dot[0], z2, e0.x); fma2(dot[1], z2, e0.y);
                fma2(dot[2], z2, e1.x); fma2(dot[3], z2, e1.y);
                fma2(dot[4], z2, e2.x); fma2(dot[5], z2, e2.y);
                fma2(dot[6], z2, e3.x); fma2(dot[7], z2, e3.y);
            }
#pragma unroll
            for (int g = 0; g < 8; g++) {
                float d0, d1; unpack2(dot[g], d0, d1);
                int kbv = cb * 64 + q * 16 + 2 * g;
                float s0 = en[q * 16 + 2 * g]     - 2.f * d0;
                float s1 = en[q * 16 + 2 * g + 1] - 2.f * d1;
                if (s0 < best) { best = s0; bidx = kbv; }
                if (s1 < best) { best = s1; bidx = kbv + 1; }
            }
        }
        // argmin across 4 lanes of this token (tie -> lower index)
#pragma unroll
        for (int off = 1; off < 4; off <<= 1) {
            float ob = __shfl_xor_sync(0xffffffffu, best, off);
            int   oi = __shfl_xor_sync(0xffffffffu, bidx, off);
            if (ob < best || (ob == best && oi < bidx)) { best = ob; bidx = oi; }
        }
        // gather codebook vector into A (in place), accumulate diff partial
        float dsum = 0.f;
#pragma unroll
        for (int dd = 0; dd < 16; dd++) {
            int d = q * 16 + dd;
            float e = __ldg(embed + d * NEMB + bidx);
            float z = Af[d * SF + jc];
            Af[d * SF + jc] = e;
            float df = e - z;
            dsum += df * df;
        }
#pragma unroll
        for (int off = 16; off > 0; off >>= 1)
            dsum += __shfl_xor_sync(0xffffffffu, dsum, off);
        if ((tid & 31) == 0) wsum[tid >> 5] = dsum;
        __syncthreads();
        if (tid == 0)
            g_part[blockIdx.x] = wsum[0] + wsum[1] + wsum[2] + wsum[3];
    }

    // ---- decoder ----
    LCONV( 8, 256,  64,  8, false, false, false, A2, B2);
    LCONV( 9,  32, 256, 64, true,  true,  false, B2, A2);
    LCONV(10, 256,  32,  8, false, false, true,  A2, B2);
    LCONV(11,  32, 256, 64, true,  true,  false, B2, A2);
    LCONV(12, 256,  32,  8, false, false, true,  A2, B2);
    LCONV(13, 128, 256, 16, true,  true,  false, B2, A2);
    LCONV(14, 256, 128,  8, false, false, false, A2, B2);   // padded to 256 ch
    __syncthreads();

    // ---- store output tile: pair layout -> [tok][c] ----
    for (int idx = tid; idx < CINN * TILE; idx += THREADS) {
        int j = idx / CINN;
        int c = idx - j * CINN;
        P.out[(n0 + j) * CINN + c] = Bf[c * SF + jcol(j)];
    }

    // ---- last-block finalize of diff ----
    __threadfence();
    __shared__ unsigned int is_last;
    if (tid == 0) is_last = (atomicAdd(&g_count, 1u) == NBLK - 1) ? 1u : 0u;
    __syncthreads();
    if (is_last) {
        float s = 0.f;
        for (int i = tid; i < NBLK; i += THREADS) s += g_part[i];
#pragma unroll
        for (int off = 16; off > 0; off >>= 1)
            s += __shfl_xor_sync(0xffffffffu, s, off);
        if ((tid & 31) == 0) wsum[tid >> 5] = s;
        __syncthreads();
        if (tid == 0) {
            float t = wsum[0] + wsum[1] + wsum[2] + wsum[3];
            if (P.out_size > DEC_ELEMS)
                P.out[DEC_ELEMS] = t * (1.0f / 8388608.0f);  // mean over N*EDIM
            g_count = 0u;   // reset for next graph replay
        }
    }
}

// ---------------- launch ----------------
extern "C" void kernel_launch(void* const* d_in, const int* in_sizes, int n_in,
                              void* d_out, int out_size)
{
    (void)in_sizes; (void)n_in;
    Params P;
    for (int i = 0; i < 32; i++) P.in[i] = (const float*)d_in[i];
    P.out = (float*)d_out;
    P.out_size = out_size;

    static bool attr_set = false;
    if (!attr_set) {
        cudaFuncSetAttribute(vqvae_kernel, cudaFuncAttributeMaxDynamicSharedMemorySize, SMEM_BYTES);
        attr_set = true;
    }
    prep_kernel<<<15, 256>>>(P);
    vqvae_kernel<<<NBLK, THREADS, SMEM_BYTES>>>(P);
}

// round 9
// speedup vs baseline: 1.3235x; 1.3235x over previous
#include <cuda_runtime.h>
#include <cstdint>

// ---------------- problem constants ----------------
#define BN   32
#define TN   4096
#define CINN 165
#define EDIM 64
#define NEMB 512
#define NTOK (BN*TN)          // 131072
#define TILE 32               // tokens per CTA
#define NBLK (NTOK/TILE)      // 4096
#define LDA  36               // padded token-row stride (floats)
#define DEC_ELEMS (NTOK*CINN) // 21626880
#define THREADS 128

// shared layout (floats): single in-place activation buffer A[288 rows]
#define AROWS  288
#define SM_A   0
#define SM_W   (AROWS*LDA)          // 10368
#define WBUFF  4096                 // floats per weight buffer (KBT*CW <= 4096)
#define SM_AUX (SM_W + 2*WBUFF)     // 18560
#define SM_FLOATS (SM_AUX + 128 + 64 + 8)
#define SMEM_BYTES (SM_FLOATS*4)    // ~73.3 KB -> 3 CTAs/SM

typedef unsigned long long ULL;

// transposed+padded weights and bias, built once per launch by prep_kernel
__device__ float g_Wt[276480];
__device__ float g_bias[2432];
__device__ float g_part[NBLK];
__device__ unsigned int g_count;

// layer metadata: {w_in_idx, b_in_idx, CIN, COUT, KPAD, CW, woff, boff}
__constant__ int c_layers[15][8] = {
    { 1,  2, 165, 128, 176, 128,      0,    0},
    { 3,  4, 128, 256, 128, 256,  22528,  128},
    { 5,  6, 256, 256, 256, 256,  55296,  384},
    { 7,  8, 256,  32, 256,  32, 120832,  640},
    { 9, 10,  32, 256,  32, 256, 129024,  672},
    {11, 12, 256,  32, 256,  32, 137216,  928},
    {13, 14,  32, 256,  32, 256, 145408,  960},
    {15, 16, 256,  64, 256,  64, 153600, 1216},
    {18, 19,  64, 256,  64, 256, 169984, 1280},
    {20, 21, 256,  32, 256,  32, 186368, 1536},
    {22, 23,  32, 256,  32, 256, 194560, 1568},
    {24, 25, 256,  32, 256,  32, 202752, 1824},
    {26, 27,  32, 256,  32, 256, 210944, 1856},
    {28, 29, 256, 128, 256, 128, 219136, 2112},
    {30, 31, 128, 165, 128, 192, 251904, 2240},
};

// ---------------- f32x2 helpers ----------------
__device__ __forceinline__ ULL pack2(float x, float y) {
    ULL r; asm("mov.b64 %0, {%1, %2};" : "=l"(r) : "f"(x), "f"(y)); return r;
}
__device__ __forceinline__ void unpack2(ULL v, float& x, float& y) {
    asm("mov.b64 {%0, %1}, %2;" : "=f"(x), "=f"(y) : "l"(v));
}
__device__ __forceinline__ void fma2(ULL& d, ULL a, ULL b) {
    asm("fma.rn.f32x2 %0, %1, %2, %0;" : "+l"(d) : "l"(a), "l"(b));
}
__device__ __forceinline__ uint32_t smem_u32(const void* p) {
    uint32_t a;
    asm("{ .reg .u64 t; cvta.to.shared.u64 t, %1; cvt.u32.u64 %0, t; }" : "=r"(a) : "l"(p));
    return a;
}
__device__ __forceinline__ void cp_async16(uint32_t dst, const void* src) {
    asm volatile("cp.async.cg.shared.global [%0], [%1], 16;\n" :: "r"(dst), "l"(src));
}

// ---------------- prep: transpose + pad weights ----------------
struct Params { const float* in[32]; float* out; int out_size; };

__global__ void prep_kernel(Params P) {
    const int L = blockIdx.x;
    const int CIN  = c_layers[L][2], COUT = c_layers[L][3];
    const int KPAD = c_layers[L][4], CW   = c_layers[L][5];
    const int woff = c_layers[L][6], boff = c_layers[L][7];
    const float* W = P.in[c_layers[L][0]];
    const float* b = P.in[c_layers[L][1]];
    for (int e = threadIdx.x; e < KPAD * CW; e += blockDim.x) {
        int k = e / CW, c = e - (e / CW) * CW;
        float v = (k < CIN && c < COUT) ? W[c * CIN + k] : 0.f;
        g_Wt[woff + e] = v;
    }
    for (int c = threadIdx.x; c < CW; c += blockDim.x)
        g_bias[boff + c] = (c < COUT) ? b[c] : 0.f;
}

// ---------------- channel ownership (bank-conflict-free quads) ----------------
template<int MT>
__device__ __forceinline__ int chan(int ty, int m) {
    if constexpr (MT == 8) return (m < 4) ? ty * 4 + m : 128 + ty * 4 + (m - 4);
    else if constexpr (MT == 6) return (m < 4) ? ty * 4 + m : 128 + ty * 2 + (m - 4);
    else if constexpr (MT == 4) return ty * 4 + m;
    else if constexpr (MT == 2) return ty * 2 + m;
    else return ty;
}

template<int MT>
__device__ __forceinline__ void load_wf(const float* Wrow, int ty, float* wf) {
    if constexpr (MT == 8) {
        float4 a = *reinterpret_cast<const float4*>(Wrow + ty * 4);
        float4 b = *reinterpret_cast<const float4*>(Wrow + 128 + ty * 4);
        wf[0] = a.x; wf[1] = a.y; wf[2] = a.z; wf[3] = a.w;
        wf[4] = b.x; wf[5] = b.y; wf[6] = b.z; wf[7] = b.w;
    } else if constexpr (MT == 6) {
        float4 a = *reinterpret_cast<const float4*>(Wrow + ty * 4);
        float2 b = *reinterpret_cast<const float2*>(Wrow + 128 + ty * 2);
        wf[0] = a.x; wf[1] = a.y; wf[2] = a.z; wf[3] = a.w;
        wf[4] = b.x; wf[5] = b.y;
    } else if constexpr (MT == 4) {
        float4 a = *reinterpret_cast<const float4*>(Wrow + ty * 4);
        wf[0] = a.x; wf[1] = a.y; wf[2] = a.z; wf[3] = a.w;
    } else if constexpr (MT == 2) {
        float2 a = *reinterpret_cast<const float2*>(Wrow + ty * 2);
        wf[0] = a.x; wf[1] = a.y;
    } else {
        wf[0] = Wrow[ty];
    }
}

// ---------------- fused 1x1-conv layer (in-place capable) ----------------
// OUT[c][t] = (RES? OUT[c][t]:0) + bias[c] + sum_k W[c][k]*(PRE? relu(IN[k][t]) : IN[k][t])
// 128 threads: 32 channel-groups (MT ch) x 4 token-groups (8 tokens)
// STAGE: OUT overlaps IN -> barrier between last read and writeback.
template<int CW, int KPAD, int KBT, bool PRE, bool POST, bool RES, bool STAGE>
__device__ __noinline__ void conv_layer(const float* __restrict__ Wt,
                                        const float* __restrict__ bias,
                                        const float* __restrict__ IN,
                                        float* __restrict__ OUT,
                                        float* __restrict__ Ws, int tid)
{
    constexpr int MT = CW / 32;
    constexpr int NK = KPAD / KBT;
    constexpr int CHUNKF = KBT * CW;
    static_assert(CHUNKF <= WBUFF, "chunk too big");

    const int tx = tid & 3;
    const int ty = tid >> 2;      // 0..31
    const int j0 = tx * 8;

    float bv[MT];
#pragma unroll
    for (int m = 0; m < MT; m++) bv[m] = __ldg(bias + chan<MT>(ty, m));

    ULL acc[4][MT];
#pragma unroll
    for (int t = 0; t < 4; t++)
#pragma unroll
        for (int m = 0; m < MT; m++) acc[t][m] = 0ull;

    __syncthreads();   // prev-layer writes visible; Ws free

    // stage chunk 0 (linear memcpy)
    {
        const float4* src = reinterpret_cast<const float4*>(Wt);
        float4* dst = reinterpret_cast<float4*>(Ws);
#pragma unroll
        for (int i = tid; i < CHUNKF / 4; i += THREADS)
            cp_async16(smem_u32(dst + i), src + i);
        asm volatile("cp.async.commit_group;\n" ::: "memory");
    }

    for (int kb = 0; kb < NK; kb++) {
        asm volatile("cp.async.wait_group 0;\n" ::: "memory");
        __syncthreads();
        if (kb + 1 < NK) {
            const float4* src = reinterpret_cast<const float4*>(Wt + (kb + 1) * CHUNKF);
            float4* dst = reinterpret_cast<float4*>(Ws + ((kb + 1) & 1) * WBUFF);
#pragma unroll
            for (int i = tid; i < CHUNKF / 4; i += THREADS)
                cp_async16(smem_u32(dst + i), src + i);
            asm volatile("cp.async.commit_group;\n" ::: "memory");
        }

        const float* Wk  = Ws + (kb & 1) * WBUFF;
        const float* inb = IN + kb * KBT * LDA + j0;

#pragma unroll 8
        for (int kk = 0; kk < KBT; kk++) {
            float4 va = *reinterpret_cast<const float4*>(inb + kk * LDA);
            float4 vb = *reinterpret_cast<const float4*>(inb + kk * LDA + 4);
            if (PRE) {
                va.x = fmaxf(va.x, 0.f); va.y = fmaxf(va.y, 0.f);
                va.z = fmaxf(va.z, 0.f); va.w = fmaxf(va.w, 0.f);
                vb.x = fmaxf(vb.x, 0.f); vb.y = fmaxf(vb.y, 0.f);
                vb.z = fmaxf(vb.z, 0.f); vb.w = fmaxf(vb.w, 0.f);
            }
            ULL t0 = pack2(va.x, va.y), t1 = pack2(va.z, va.w);
            ULL t2 = pack2(vb.x, vb.y), t3 = pack2(vb.z, vb.w);
            float wf[MT];
            load_wf<MT>(Wk + kk * CW, ty, wf);
#pragma unroll
            for (int m = 0; m < MT; m++) {
                ULL wd = pack2(wf[m], wf[m]);
                fma2(acc[0][m], wd, t0);
                fma2(acc[1][m], wd, t1);
                fma2(acc[2][m], wd, t2);
                fma2(acc[3][m], wd, t3);
            }
        }
    }

    // in-place staging barrier: all threads finished reading IN
    if (STAGE) __syncthreads();

    // epilogue: thread exclusively owns (ch, 8-token) slots of OUT
#pragma unroll
    for (int m = 0; m < MT; m++) {
        float r[8];
        unpack2(acc[0][m], r[0], r[1]);
        unpack2(acc[1][m], r[2], r[3]);
        unpack2(acc[2][m], r[4], r[5]);
        unpack2(acc[3][m], r[6], r[7]);
        float* op = OUT + chan<MT>(ty, m) * LDA + j0;
        float4 o0, o1;
        o0.x = r[0] + bv[m]; o0.y = r[1] + bv[m];
        o0.z = r[2] + bv[m]; o0.w = r[3] + bv[m];
        o1.x = r[4] + bv[m]; o1.y = r[5] + bv[m];
        o1.z = r[6] + bv[m]; o1.w = r[7] + bv[m];
        if (RES) {
            float4 e0 = *reinterpret_cast<float4*>(op);
            float4 e1 = *reinterpret_cast<float4*>(op + 4);
            o0.x += e0.x; o0.y += e0.y; o0.z += e0.z; o0.w += e0.w;
            o1.x += e1.x; o1.y += e1.y; o1.z += e1.z; o1.w += e1.w;
        }
        if (POST) {
            o0.x = fmaxf(o0.x, 0.f); o0.y = fmaxf(o0.y, 0.f);
            o0.z = fmaxf(o0.z, 0.f); o0.w = fmaxf(o0.w, 0.f);
            o1.x = fmaxf(o1.x, 0.f); o1.y = fmaxf(o1.y, 0.f);
            o1.z = fmaxf(o1.z, 0.f); o1.w = fmaxf(o1.w, 0.f);
        }
        *reinterpret_cast<float4*>(op)     = o0;
        *reinterpret_cast<float4*>(op + 4) = o1;
    }
}

#define LCONV(L, CW, KPAD, KBT, PRE, POST, RES, STAGE, INB, OUTB) \
    conv_layer<CW, KPAD, KBT, PRE, POST, RES, STAGE>(g_Wt + c_layers[L][6], g_bias + c_layers[L][7], INB, OUTB, Ws, tid)

// ---------------- main fused kernel ----------------
__global__ void __launch_bounds__(THREADS, 3) vqvae_kernel(Params P)
{
    extern __shared__ float sm[];
    float* A    = sm + SM_A;             // 288 rows x LDA
    float* T32  = A + 256 * LDA;         // resblock intermediate rows 256..287
    float* Ws   = sm + SM_W;
    float* enp  = sm + SM_AUX;           // [128]
    float* en   = enp + 128;             // [64]
    float* wsum = en + 64;               // [8]

    const int tid = threadIdx.x;
    const int n0  = blockIdx.x * TILE;

    // ---- load x tile: [tok][c] -> [c][tok]; zero-pad rows 165..175 ----
    const float* x = P.in[0];
    for (int idx = tid; idx < 176 * TILE; idx += THREADS) {
        int c = idx % 176;
        int j = idx / 176;
        A[c * LDA + j] = (c < CINN) ? x[(n0 + j) * CINN + c] : 0.f;
    }

    // ---- encoder (all in-place in A; resblock mids in T32) ----
    LCONV(0, 128, 176, 16, false, true,  false, true,  A,   A  );
    LCONV(1, 256, 128, 16, false, true,  false, true,  A,   A  );
    LCONV(2, 256, 256, 16, false, false, false, true,  A,   A  );
    LCONV(3,  32, 256, 128, true, true,  false, false, A,   T32);
    LCONV(4, 256,  32, 16, false, false, true,  false, T32, A  );
    LCONV(5,  32, 256, 128, true, true,  false, false, A,   T32);
    LCONV(6, 256,  32, 16, false, false, true,  false, T32, A  );
    LCONV(7,  64, 256, 64, true,  false, false, true,  A,   A  );   // z -> rows 0..63

    // ---- vector quantize (z in A rows 0..63) ----
    {
        const float* embed = P.in[17];
        float* Es = Ws;                 // [64 d][64 codes] = 16KB
        const int j = tid >> 2;         // token 0..31
        const int q = tid & 3;          // code 16-chunk within 64-code block
        float best = 3.4e38f; int bidx = 0;

        for (int cb = 0; cb < 8; cb++) {
            __syncthreads();
            float sq = 0.f;
#pragma unroll
            for (int i = 0; i < 32; i++) {
                int idx = i * THREADS + tid;
                int kk = idx & 63, d = idx >> 6;
                float v = __ldg(embed + d * NEMB + cb * 64 + kk);
                Es[d * 64 + kk] = v;
                sq += v * v;            // all iterations share kk = tid&63
            }
            enp[tid] = sq;
            __syncthreads();
            if (tid < 64) en[tid] = enp[tid] + enp[tid + 64];
            __syncthreads();

            ULL dot[8];
#pragma unroll
            for (int g = 0; g < 8; g++) dot[g] = 0ull;
#pragma unroll 8
            for (int d = 0; d < EDIM; d++) {
                float z = A[d * LDA + j];
                ULL z2 = pack2(z, z);
                const ulonglong2* er = reinterpret_cast<const ulonglong2*>(Es + d * 64 + q * 16);
                ulonglong2 e0 = er[0], e1 = er[1], e2 = er[2], e3 = er[3];
                fma2(dot[0], z2, e0.x); fma2(dot[1], z2, e0.y);
                fma2(dot[2], z2, e1.x); fma2(dot[3], z2, e1.y);
                fma2(dot[4], z2, e2.x); fma2(dot[5], z2, e2.y);
                fma2(dot[6], z2, e3.x); fma2(dot[7], z2, e3.y);
            }
#pragma unroll
            for (int g = 0; g < 8; g++) {
                float d0, d1; unpack2(dot[g], d0, d1);
                int kbv = cb * 64 + q * 16 + 2 * g;
                float s0 = en[q * 16 + 2 * g]     - 2.f * d0;
                float s1 = en[q * 16 + 2 * g + 1] - 2.f * d1;
                if (s0 < best) { best = s0; bidx = kbv; }
                if (s1 < best) { best = s1; bidx = kbv + 1; }
            }
        }
        // argmin across 4 lanes of this token (tie -> lower index);
        // shuffle also converges the warp before in-place writes below.
#pragma unroll
        for (int off = 1; off < 4; off <<= 1) {
            float ob = __shfl_xor_sync(0xffffffffu, best, off);
            int   oi = __shfl_xor_sync(0xffffffffu, bidx, off);
            if (ob < best || (ob == best && oi < bidx)) { best = ob; bidx = oi; }
        }
        // gather codebook vector into A (in place), accumulate diff partial
        float dsum = 0.f;
#pragma unroll
        for (int dd = 0; dd < 16; dd++) {
            int d = q * 16 + dd;
            float e = __ldg(embed + d * NEMB + bidx);
            float z = A[d * LDA + j];
            A[d * LDA + j] = e;
            float df = e - z;
            dsum += df * df;
        }
#pragma unroll
        for (int off = 16; off > 0; off >>= 1)
            dsum += __shfl_xor_sync(0xffffffffu, dsum, off);
        if ((tid & 31) == 0) wsum[tid >> 5] = dsum;
        __syncthreads();
        if (tid == 0)
            g_part[blockIdx.x] = wsum[0] + wsum[1] + wsum[2] + wsum[3];
    }

    // ---- decoder ----
    LCONV( 8, 256,  64, 16, false, false, false, true,  A,   A  );
    LCONV( 9,  32, 256, 128, true, true,  false, false, A,   T32);
    LCONV(10, 256,  32, 16, false, false, true,  false, T32, A  );
    LCONV(11,  32, 256, 128, true, true,  false, false, A,   T32);
    LCONV(12, 256,  32, 16, false, false, true,  false, T32, A  );
    LCONV(13, 128, 256, 32, true,  true,  false, true,  A,   A  );
    LCONV(14, 192, 128, 16, false, false, false, true,  A,   A  );
    __syncthreads();

    // ---- store output tile: [c][tok] -> [tok][c] ----
    for (int idx = tid; idx < CINN * TILE; idx += THREADS) {
        int j = idx / CINN;
        int c = idx - j * CINN;
        P.out[(n0 + j) * CINN + c] = A[c * LDA + j];
    }

    // ---- last-block finalize of diff ----
    __threadfence();
    __shared__ unsigned int is_last;
    if (tid == 0) is_last = (atomicAdd(&g_count, 1u) == NBLK - 1) ? 1u : 0u;
    __syncthreads();
    if (is_last) {
        float s = 0.f;
        for (int i = tid; i < NBLK; i += THREADS) s += g_part[i];
#pragma unroll
        for (int off = 16; off > 0; off >>= 1)
            s += __shfl_xor_sync(0xffffffffu, s, off);
        if ((tid & 31) == 0) wsum[tid >> 5] = s;
        __syncthreads();
        if (tid == 0) {
            float t = wsum[0] + wsum[1] + wsum[2] + wsum[3];
            if (P.out_size > DEC_ELEMS)
                P.out[DEC_ELEMS] = t * (1.0f / 8388608.0f);  // mean over N*EDIM
            g_count = 0u;   // reset for next graph replay
        }
    }
}

// ---------------- launch ----------------
extern "C" void kernel_launch(void* const* d_in, const int* in_sizes, int n_in,
                              void* d_out, int out_size)
{
    (void)in_sizes; (void)n_in;
    Params P;
    for (int i = 0; i < 32; i++) P.in[i] = (const float*)d_in[i];
    P.out = (float*)d_out;
    P.out_size = out_size;

    static bool attr_set = false;
    if (!attr_set) {
        cudaFuncSetAttribute(vqvae_kernel, cudaFuncAttributeMaxDynamicSharedMemorySize, SMEM_BYTES);
        attr_set = true;
    }
    prep_kernel<<<15, 256>>>(P);
    vqvae_kernel<<<NBLK, THREADS, SMEM_BYTES>>>(P);
}